// round 12
// baseline (speedup 1.0000x reference)
#include <cuda_runtime.h>
#include <math.h>

// ---------------- problem constants ----------------
#define B_   64
#define C_   256
#define HW_  4096            // 64*64
#define TPB_ 128             // tiles (32-pos) per batch
#define NBLK 9               // CTAs per batch -> grid 576 <= 608 (4 CTAs/SM x 152)
#define PLANES 128
#define HIDDEN 16
#define K_   8
#define ATT_CH 4
#define EPS_ 1e-5f

// ---------------- device scratch (zero-init at load; last CTA re-zeros) ----------------
__device__ float    g_sumc[B_ * C_];
__device__ float    g_num [B_ * C_];
__device__ float    g_D   [B_];
__device__ float    g_summ[B_];
__device__ unsigned g_cnt [B_];

__global__ __launch_bounds__(128, 4) void fused(
        const float* __restrict__ x,
        const float* __restrict__ w_mask, const float* __restrict__ b_mask,
        const float* __restrict__ w_cm1, const float* __restrict__ b_cm1,
        const float* __restrict__ ln_w,  const float* __restrict__ ln_b,
        const float* __restrict__ w_cm2, const float* __restrict__ b_cm2,
        const float* __restrict__ w_net1, const float* __restrict__ w_net2,
        const float* __restrict__ w_fc,
        const float* __restrict__ bn_w,  const float* __restrict__ bn_b,
        const float* __restrict__ bn_mean, const float* __restrict__ bn_var,
        const float* __restrict__ w_kfc,
        float* __restrict__ out) {
    // static smem: AL[4][32] + AM[4][32] partials; finalize reuses [0..1081)
    __shared__ __align__(16) float sm[1104];
    __shared__ int s_last;
    float* AL = sm;          // [4 warps][32 positions] logit partials
    float* AM = sm + 128;    // [4 warps][32 positions] max partials

    const int t    = threadIdx.x;    // 0..127
    const int lane = t & 31;
    const int w    = t >> 5;         // warp 0..3
    const int b    = blockIdx.x / NBLK;
    const int j    = blockIdx.x - b * NBLK;   // 0..8 within batch

    // tile split: 2 CTAs x 15 + 7 CTAs x 14 = 128 tiles per batch
    const int my_count = (j < 2) ? 15 : 14;
    const int tile0    = (j < 2) ? j * 15 : 30 + (j - 2) * 14;

    const int cg = t >> 2;           // channel group 0..31 (channels cg*8+i)
    const int q  = t & 3;            // this thread's float4 columns: q and q+4

    // hoisted mask weights for this thread's 8 channels
    float4 wv0 = *reinterpret_cast<const float4*>(w_mask + cg * 8);
    float4 wv1 = *reinterpret_cast<const float4*>(w_mask + cg * 8 + 4);
    const float wreg[8] = {wv0.x, wv0.y, wv0.z, wv0.w, wv1.x, wv1.y, wv1.z, wv1.w};
    const float bm = b_mask[0];

    // thread-fixed row pointer: batch base + first channel row + column q
    const float4* xr = reinterpret_cast<const float4*>(x) + (size_t)b * C_ * (HW_ / 4)
                     + (size_t)(cg * 8) * (HW_ / 4) + q;

    // per-thread accumulators (channel cg*8+i over this thread's 8 positions)
    float sv[8], sve[8];
    #pragma unroll
    for (int i = 0; i < 8; ++i) { sv[i] = 0.f; sve[i] = 0.f; }
    float run_e = 0.f, run_m = 0.f;     // warp 0 lanes

    for (int sub = 0; sub < my_count; ++sub) {
        const size_t base = (size_t)(tile0 + sub) * 8;

        // ---- 16 independent coalesced LDG.128 (2KB per warp in flight) ----
        // d_a: positions q*4..q*4+3 ; d_b: positions 16+q*4..16+q*4+3
        float4 da[8], db[8];
        #pragma unroll
        for (int i = 0; i < 8; ++i) {
            da[i] = __ldg(xr + (size_t)i * (HW_ / 4) + base);
            db[i] = __ldg(xr + (size_t)i * (HW_ / 4) + base + 4);
        }

        // ---- phase2: logit / max / channel-sum partials ----
        float4 lpA = make_float4(0.f, 0.f, 0.f, 0.f);
        float4 lpB = make_float4(0.f, 0.f, 0.f, 0.f);
        float4 mpA = make_float4(-1e30f, -1e30f, -1e30f, -1e30f);
        float4 mpB = make_float4(-1e30f, -1e30f, -1e30f, -1e30f);
        #pragma unroll
        for (int i = 0; i < 8; ++i) {
            const float wc = wreg[i];
            lpA.x = fmaf(da[i].x, wc, lpA.x); lpA.y = fmaf(da[i].y, wc, lpA.y);
            lpA.z = fmaf(da[i].z, wc, lpA.z); lpA.w = fmaf(da[i].w, wc, lpA.w);
            lpB.x = fmaf(db[i].x, wc, lpB.x); lpB.y = fmaf(db[i].y, wc, lpB.y);
            lpB.z = fmaf(db[i].z, wc, lpB.z); lpB.w = fmaf(db[i].w, wc, lpB.w);
            mpA.x = fmaxf(mpA.x, da[i].x);    mpA.y = fmaxf(mpA.y, da[i].y);
            mpA.z = fmaxf(mpA.z, da[i].z);    mpA.w = fmaxf(mpA.w, da[i].w);
            mpB.x = fmaxf(mpB.x, db[i].x);    mpB.y = fmaxf(mpB.y, db[i].y);
            mpB.z = fmaxf(mpB.z, db[i].z);    mpB.w = fmaxf(mpB.w, db[i].w);
            sv[i] += (da[i].x + da[i].y) + (da[i].z + da[i].w)
                   + (db[i].x + db[i].y) + (db[i].z + db[i].w);
        }
        // intra-warp reduce over the 8 channel-groups (lanes stride 4, same q)
        #pragma unroll
        for (int off = 4; off <= 16; off <<= 1) {
            lpA.x += __shfl_down_sync(0xffffffffu, lpA.x, off);
            lpA.y += __shfl_down_sync(0xffffffffu, lpA.y, off);
            lpA.z += __shfl_down_sync(0xffffffffu, lpA.z, off);
            lpA.w += __shfl_down_sync(0xffffffffu, lpA.w, off);
            lpB.x += __shfl_down_sync(0xffffffffu, lpB.x, off);
            lpB.y += __shfl_down_sync(0xffffffffu, lpB.y, off);
            lpB.z += __shfl_down_sync(0xffffffffu, lpB.z, off);
            lpB.w += __shfl_down_sync(0xffffffffu, lpB.w, off);
            mpA.x = fmaxf(mpA.x, __shfl_down_sync(0xffffffffu, mpA.x, off));
            mpA.y = fmaxf(mpA.y, __shfl_down_sync(0xffffffffu, mpA.y, off));
            mpA.z = fmaxf(mpA.z, __shfl_down_sync(0xffffffffu, mpA.z, off));
            mpA.w = fmaxf(mpA.w, __shfl_down_sync(0xffffffffu, mpA.w, off));
            mpB.x = fmaxf(mpB.x, __shfl_down_sync(0xffffffffu, mpB.x, off));
            mpB.y = fmaxf(mpB.y, __shfl_down_sync(0xffffffffu, mpB.y, off));
            mpB.z = fmaxf(mpB.z, __shfl_down_sync(0xffffffffu, mpB.z, off));
            mpB.w = fmaxf(mpB.w, __shfl_down_sync(0xffffffffu, mpB.w, off));
        }
        __syncthreads();     // BAR A: previous combine reads of AL/AM are done
        if (lane < 4) {      // lanes 0..3 hold q = 0..3
            *reinterpret_cast<float4*>(AL + w * 32 + lane * 4)      = lpA;
            *reinterpret_cast<float4*>(AL + w * 32 + 16 + lane * 4) = lpB;
            *reinterpret_cast<float4*>(AM + w * 32 + lane * 4)      = mpA;
            *reinterpret_cast<float4*>(AM + w * 32 + 16 + lane * 4) = mpB;
        }
        __syncthreads();     // BAR B: partials visible

        // ---- combine (every warp redundantly; lane = position) ----
        float l = bm;
        #pragma unroll
        for (int p = 0; p < 4; ++p) l += AL[p * 32 + lane];
        const float e = __expf(l);       // unnormalized softmax weight (logits O(3))
        if (w == 0) {
            run_e += e;
            float m = -1e30f;
            #pragma unroll
            for (int p = 0; p < 4; ++p) m = fmaxf(m, AM[p * 32 + lane]);
            run_m += m;
        }

        // ---- phase3: weighted accumulate from the SAME registers ----
        const float eA0 = __shfl_sync(0xffffffffu, e, q * 4 + 0);
        const float eA1 = __shfl_sync(0xffffffffu, e, q * 4 + 1);
        const float eA2 = __shfl_sync(0xffffffffu, e, q * 4 + 2);
        const float eA3 = __shfl_sync(0xffffffffu, e, q * 4 + 3);
        const float eB0 = __shfl_sync(0xffffffffu, e, 16 + q * 4 + 0);
        const float eB1 = __shfl_sync(0xffffffffu, e, 16 + q * 4 + 1);
        const float eB2 = __shfl_sync(0xffffffffu, e, 16 + q * 4 + 2);
        const float eB3 = __shfl_sync(0xffffffffu, e, 16 + q * 4 + 3);
        #pragma unroll
        for (int i = 0; i < 8; ++i) {
            float a = fmaf(da[i].x, eA0, sve[i]);
            a = fmaf(da[i].y, eA1, a);
            a = fmaf(da[i].z, eA2, a);
            a = fmaf(da[i].w, eA3, a);
            a = fmaf(db[i].x, eB0, a);
            a = fmaf(db[i].y, eB1, a);
            a = fmaf(db[i].z, eB2, a);
            sve[i] = fmaf(db[i].w, eB3, a);
        }
    }

    // ---- reduce sv/sve over the 4 q-lanes of each channel group ----
    #pragma unroll
    for (int off = 1; off <= 2; off <<= 1) {
        #pragma unroll
        for (int i = 0; i < 8; ++i) {
            sv[i]  += __shfl_down_sync(0xffffffffu, sv[i],  off, 4);
            sve[i] += __shfl_down_sync(0xffffffffu, sve[i], off, 4);
        }
    }
    if (q == 0) {
        #pragma unroll
        for (int i = 0; i < 8; ++i) {
            atomicAdd(&g_sumc[b * C_ + cg * 8 + i], sv[i]);
            atomicAdd(&g_num [b * C_ + cg * 8 + i], sve[i]);
        }
    }
    if (w == 0) {
        #pragma unroll
        for (int off = 16; off > 0; off >>= 1) {
            run_e += __shfl_down_sync(0xffffffffu, run_e, off);
            run_m += __shfl_down_sync(0xffffffffu, run_m, off);
        }
        if (lane == 0) { atomicAdd(&g_D[b], run_e); atomicAdd(&g_summ[b], run_m); }
    }
    __threadfence();
    __syncthreads();
    if (t == 0) {
        unsigned old = atomicAdd(&g_cnt[b], 1u);
        s_last = (old == NBLK - 1);
    }
    __syncthreads();
    if (!s_last) return;

    // ================= finalize (last CTA of this batch; 128 threads) =================
    float* ctx   = sm;            // 256  (aliases AL/AM — loop fully done)
    float* bcv   = sm + 256;      // 256
    float* tvs   = sm + 512;      // 128
    float* tg    = sm + 640;      // 128
    float* sout  = sm + 768;      // 256
    float* red_s = sm + 1024;     // 4
    float* red_q = sm + 1028;     // 4
    float* red_a = sm + 1032;     // 4
    float* hid   = sm + 1040;     // 16
    float* o8    = sm + 1056;     // 8
    float* kar   = sm + 1064;     // 4
    float* fvv   = sm + 1072;     // 8
    float* shm   = sm + 1080;     // 1

    const int wp = w;

    const float Dv    = __ldcg(&g_D[b]);
    const float summv = __ldcg(&g_summ[b]);
    const float num0  = __ldcg(&g_num [b * C_ + t]);
    const float num1  = __ldcg(&g_num [b * C_ + t + 128]);
    const float sum0  = __ldcg(&g_sumc[b * C_ + t]);
    const float sum1  = __ldcg(&g_sumc[b * C_ + t + 128]);

    const float invD = 1.f / Dv;
    ctx[t]       = num0 * invD;
    ctx[t + 128] = num1 * invD;
    bcv[t]       = sum0 * (1.f / (float)HW_);
    bcv[t + 128] = sum1 * (1.f / (float)HW_);
    {
        float s = (sum0 + sum1) * (1.f / (float)HW_);
        #pragma unroll
        for (int off = 16; off > 0; off >>= 1) s += __shfl_down_sync(0xffffffffu, s, off);
        if (lane == 0) red_a[wp] = s;
    }
    __syncthreads();   // all threads have loaded g_* before any re-zero (race fix)

    // re-zero scratch for next graph replay
    g_num [b * C_ + t] = 0.f;       g_num [b * C_ + t + 128] = 0.f;
    g_sumc[b * C_ + t] = 0.f;       g_sumc[b * C_ + t + 128] = 0.f;
    if (t == 0) { g_D[b] = 0.f; g_summ[b] = 0.f; g_cnt[b] = 0u; shm[0] = summv * (1.f / (float)HW_); }
    __syncthreads();

    const float aval = (red_a[0] + red_a[1] + red_a[2] + red_a[3]) * (1.f / (float)C_);
    const float mv = shm[0];

    // conv1 (128x256): warp wp -> planes wp*32..+31
    {
        const float4* ctx4 = reinterpret_cast<const float4*>(ctx);
        const float4 c0 = ctx4[lane];
        const float4 c1 = ctx4[lane + 32];
        #pragma unroll 4
        for (int i = 0; i < 32; ++i) {
            int p = wp * 32 + i;
            const float4* w4 = reinterpret_cast<const float4*>(w_cm1 + p * C_);
            float4 a0 = w4[lane];
            float4 a1 = w4[lane + 32];
            float pr = a0.x * c0.x + a0.y * c0.y + a0.z * c0.z + a0.w * c0.w
                     + a1.x * c1.x + a1.y * c1.y + a1.z * c1.z + a1.w * c1.w;
            #pragma unroll
            for (int off = 16; off > 0; off >>= 1)
                pr += __shfl_down_sync(0xffffffffu, pr, off);
            if (lane == 0) tvs[p] = pr + b_cm1[p];
        }
    }
    __syncthreads();

    // LayerNorm(128) + exact GELU (128 threads, one plane each)
    {
        float tvv = tvs[t];
        float s1 = tvv, s2 = tvv * tvv;
        #pragma unroll
        for (int off = 16; off > 0; off >>= 1) {
            s1 += __shfl_down_sync(0xffffffffu, s1, off);
            s2 += __shfl_down_sync(0xffffffffu, s2, off);
        }
        if (lane == 0) { red_s[wp] = s1; red_q[wp] = s2; }
        __syncthreads();
        {
            float S  = red_s[0] + red_s[1] + red_s[2] + red_s[3];
            float SQ = red_q[0] + red_q[1] + red_q[2] + red_q[3];
            float mu  = S * (1.f / PLANES);
            float var = SQ * (1.f / PLANES) - mu * mu;
            float tn = (tvv - mu) * rsqrtf(var + EPS_) * ln_w[t] + ln_b[t];
            tg[t] = 0.5f * tn * (1.f + erff(tn * 0.70710678118654752f));
        }
    }
    __syncthreads();

    // conv2 (256x128): warp wp -> channels wp*64..+63
    {
        const float4* tg4 = reinterpret_cast<const float4*>(tg);
        const float4 g0 = tg4[lane];
        #pragma unroll 4
        for (int i = 0; i < 64; ++i) {
            int ch = wp * 64 + i;
            const float4* w4 = reinterpret_cast<const float4*>(w_cm2 + ch * PLANES);
            float4 a0 = w4[lane];
            float pr = a0.x * g0.x + a0.y * g0.y + a0.z * g0.z + a0.w * g0.w;
            #pragma unroll
            for (int off = 16; off > 0; off >>= 1)
                pr += __shfl_down_sync(0xffffffffu, pr, off);
            if (lane == 0)
                sout[ch] = bcv[ch] + pr + b_cm2[ch] + ((ch & 1) ? mv : aval);
        }
    }
    __syncthreads();

    // net1 (16x256): warp wp -> hidden wp*4..+3
    {
        const float4* so4 = reinterpret_cast<const float4*>(sout);
        const float4 s0 = so4[lane];
        const float4 s1v = so4[lane + 32];
        #pragma unroll
        for (int jj = 0; jj < 4; ++jj) {
            int hh = wp * 4 + jj;
            const float4* w4 = reinterpret_cast<const float4*>(w_net1 + hh * C_);
            float4 a0 = w4[lane];
            float4 a1 = w4[lane + 32];
            float pr = a0.x * s0.x + a0.y * s0.y + a0.z * s0.z + a0.w * s0.w
                     + a1.x * s1v.x + a1.y * s1v.y + a1.z * s1v.z + a1.w * s1v.w;
            #pragma unroll
            for (int off = 16; off > 0; off >>= 1)
                pr += __shfl_down_sync(0xffffffffu, pr, off);
            if (lane == 0) hid[hh] = fmaxf(pr, 0.f);
        }
    }
    __syncthreads();

    if (t < K_) {
        float o = 0.f;
        #pragma unroll
        for (int q2 = 0; q2 < HIDDEN; ++q2) o = fmaf(hid[q2], w_net2[t * HIDDEN + q2], o);
        o8[t] = o;
    }
    __syncthreads();
    if (t < ATT_CH) {
        float ka = 0.f;
        #pragma unroll
        for (int k = 0; k < K_; ++k) ka = fmaf(o8[k], w_fc[t * K_ + k], ka);
        ka = (ka - bn_mean[t]) * rsqrtf(bn_var[t] + EPS_) * bn_w[t] + bn_b[t];
        kar[t] = fmaxf(ka, 0.f);
    }
    __syncthreads();
    if (t < K_) {
        float kk = 0.f;
        #pragma unroll
        for (int q2 = 0; q2 < ATT_CH; ++q2) kk = fmaf(kar[q2], w_kfc[t * ATT_CH + q2], kk);
        float ker = 1.f / (1.f + __expf(-kk));
        fvv[t] = o8[t] * ker * (1.f / 30.f);
    }
    __syncthreads();
    if (t == 0) {
        float mx = -1e30f;
        #pragma unroll
        for (int k = 0; k < K_; ++k) mx = fmaxf(mx, fvv[k]);
        float e[K_], s = 0.f;
        #pragma unroll
        for (int k = 0; k < K_; ++k) { e[k] = __expf(fvv[k] - mx); s += e[k]; }
        float inv = 1.f / s;
        #pragma unroll
        for (int k = 0; k < K_; ++k) out[b * K_ + k] = e[k] * inv;
    }
}

// ---------------- launch ----------------
extern "C" void kernel_launch(void* const* d_in, const int* in_sizes, int n_in,
                              void* d_out, int out_size) {
    const float* x      = (const float*)d_in[0];
    const float* w_mask = (const float*)d_in[1];
    const float* b_mask = (const float*)d_in[2];
    const float* w_cm1  = (const float*)d_in[3];
    const float* b_cm1  = (const float*)d_in[4];
    const float* ln_w   = (const float*)d_in[5];
    const float* ln_b   = (const float*)d_in[6];
    const float* w_cm2  = (const float*)d_in[7];
    const float* b_cm2  = (const float*)d_in[8];
    const float* w_net1 = (const float*)d_in[9];
    const float* w_net2 = (const float*)d_in[10];
    const float* w_fc   = (const float*)d_in[11];
    const float* bn_w   = (const float*)d_in[12];
    const float* bn_b   = (const float*)d_in[13];
    const float* bn_mean= (const float*)d_in[14];
    const float* bn_var = (const float*)d_in[15];
    const float* w_kfc  = (const float*)d_in[16];
    float* out = (float*)d_out;

    fused<<<B_ * NBLK, 128>>>(x, w_mask, b_mask,
                          w_cm1, b_cm1, ln_w, ln_b, w_cm2, b_cm2,
                          w_net1, w_net2, w_fc, bn_w, bn_b, bn_mean, bn_var,
                          w_kfc, out);
}

// round 13
// speedup vs baseline: 1.1120x; 1.1120x over previous
#include <cuda_runtime.h>
#include <math.h>

// ---------------- problem constants ----------------
#define B_   64
#define C_   256
#define HW_  4096            // 64*64
#define TPB_ 128             // tiles (32-pos) per batch
#define NBLK 4               // CTAs per batch -> grid 256 <= 304 (2 CTAs/SM x 152)
#define PLANES 128
#define HIDDEN 16
#define K_   8
#define ATT_CH 4
#define EPS_ 1e-5f

// ---------------- device scratch (zero-init at load; last CTA re-zeros) ----------------
__device__ float    g_sumc[B_ * C_];
__device__ float    g_num [B_ * C_];
__device__ float    g_D   [B_];
__device__ float    g_summ[B_];
__device__ unsigned g_cnt [B_];

// one tile-step: phase2 on D[], store partials to slot, barrier, combine, phase3.
// Loads for the NEXT tile were already issued into the other register set by caller.
#define TILE_STEP(D, SLOT)                                                          \
    {                                                                               \
        float4 lp = make_float4(0.f, 0.f, 0.f, 0.f);                                \
        float4 mp = make_float4(-1e30f, -1e30f, -1e30f, -1e30f);                    \
        _Pragma("unroll")                                                           \
        for (int i = 0; i < 8; ++i) {                                               \
            const float wc = wreg[i];                                               \
            lp.x = fmaf(D[i].x, wc, lp.x); lp.y = fmaf(D[i].y, wc, lp.y);           \
            lp.z = fmaf(D[i].z, wc, lp.z); lp.w = fmaf(D[i].w, wc, lp.w);           \
            mp.x = fmaxf(mp.x, D[i].x);    mp.y = fmaxf(mp.y, D[i].y);              \
            mp.z = fmaxf(mp.z, D[i].z);    mp.w = fmaxf(mp.w, D[i].w);              \
            sv[i] += (D[i].x + D[i].y) + (D[i].z + D[i].w);                         \
        }                                                                           \
        _Pragma("unroll")                                                           \
        for (int off = 8; off <= 16; off <<= 1) {                                   \
            lp.x += __shfl_down_sync(0xffffffffu, lp.x, off);                       \
            lp.y += __shfl_down_sync(0xffffffffu, lp.y, off);                       \
            lp.z += __shfl_down_sync(0xffffffffu, lp.z, off);                       \
            lp.w += __shfl_down_sync(0xffffffffu, lp.w, off);                       \
            mp.x = fmaxf(mp.x, __shfl_down_sync(0xffffffffu, mp.x, off));           \
            mp.y = fmaxf(mp.y, __shfl_down_sync(0xffffffffu, mp.y, off));           \
            mp.z = fmaxf(mp.z, __shfl_down_sync(0xffffffffu, mp.z, off));           \
            mp.w = fmaxf(mp.w, __shfl_down_sync(0xffffffffu, mp.w, off));           \
        }                                                                           \
        if (lane < 8) {                                                             \
            *reinterpret_cast<float4*>(AL + (SLOT) * 256 + w * 32 + lane * 4) = lp; \
            *reinterpret_cast<float4*>(AM + (SLOT) * 256 + w * 32 + lane * 4) = mp; \
        }                                                                           \
        __syncthreads();   /* the ONLY barrier per tile */                          \
        float l = bm;                                                               \
        _Pragma("unroll")                                                           \
        for (int p = 0; p < 8; ++p) l += AL[(SLOT) * 256 + p * 32 + lane];          \
        const float e = __expf(l);                                                  \
        if (w == 0) {                                                               \
            run_e += e;                                                             \
            float m = -1e30f;                                                       \
            _Pragma("unroll")                                                       \
            for (int p = 0; p < 8; ++p)                                             \
                m = fmaxf(m, AM[(SLOT) * 256 + p * 32 + lane]);                     \
            run_m += m;                                                             \
        }                                                                           \
        const float e0 = __shfl_sync(0xffffffffu, e, q * 4 + 0);                    \
        const float e1 = __shfl_sync(0xffffffffu, e, q * 4 + 1);                    \
        const float e2 = __shfl_sync(0xffffffffu, e, q * 4 + 2);                    \
        const float e3 = __shfl_sync(0xffffffffu, e, q * 4 + 3);                    \
        _Pragma("unroll")                                                           \
        for (int i = 0; i < 8; ++i) {                                               \
            float a = fmaf(D[i].x, e0, sve[i]);                                     \
            a = fmaf(D[i].y, e1, a);                                                \
            a = fmaf(D[i].z, e2, a);                                                \
            sve[i] = fmaf(D[i].w, e3, a);                                           \
        }                                                                           \
    }

#define LOAD_TILE(D, TI)                                                            \
    {                                                                               \
        const size_t _o = (size_t)(TI) * 8;                                         \
        _Pragma("unroll")                                                           \
        for (int i = 0; i < 8; ++i)                                                 \
            D[i] = __ldg(xr + (size_t)i * (HW_ / 4) + _o);                          \
    }

__global__ __launch_bounds__(256, 2) void fused(
        const float* __restrict__ x,
        const float* __restrict__ w_mask, const float* __restrict__ b_mask,
        const float* __restrict__ w_cm1, const float* __restrict__ b_cm1,
        const float* __restrict__ ln_w,  const float* __restrict__ ln_b,
        const float* __restrict__ w_cm2, const float* __restrict__ b_cm2,
        const float* __restrict__ w_net1, const float* __restrict__ w_net2,
        const float* __restrict__ w_fc,
        const float* __restrict__ bn_w,  const float* __restrict__ bn_b,
        const float* __restrict__ bn_mean, const float* __restrict__ bn_var,
        const float* __restrict__ w_kfc,
        float* __restrict__ out) {
    // static smem: double-buffered AL/AM (2 x [8][32] each); finalize reuses [0..1081)
    __shared__ __align__(16) float sm[1104];
    __shared__ int s_last;
    float* AL = sm;          // 2 slots x 256 floats
    float* AM = sm + 512;    // 2 slots x 256 floats

    const int t    = threadIdx.x;    // 0..255
    const int lane = t & 31;
    const int w    = t >> 5;
    const int b    = blockIdx.x >> 2;
    const int j    = blockIdx.x & 3;          // 0..3 within batch

    const int tile0 = j * 32;        // 32 tiles (32 positions each) per CTA

    const int cg = t >> 3;           // channel group 0..31 (channels cg*8+i)
    const int q  = t & 7;            // position quad 0..7

    // hoisted mask weights for this thread's 8 channels
    float4 wv0 = *reinterpret_cast<const float4*>(w_mask + cg * 8);
    float4 wv1 = *reinterpret_cast<const float4*>(w_mask + cg * 8 + 4);
    const float wreg[8] = {wv0.x, wv0.y, wv0.z, wv0.w, wv1.x, wv1.y, wv1.z, wv1.w};
    const float bm = b_mask[0];

    // thread-fixed row pointer
    const float4* xr = reinterpret_cast<const float4*>(x) + (size_t)b * C_ * (HW_ / 4)
                     + (size_t)(cg * 8) * (HW_ / 4) + q;

    // accumulators
    float sv[8], sve[8];
    #pragma unroll
    for (int i = 0; i < 8; ++i) { sv[i] = 0.f; sve[i] = 0.f; }
    float run_e = 0.f, run_m = 0.f;     // warp 0 lanes

    float4 dA[8], dB[8];
    LOAD_TILE(dA, tile0)                       // prologue: tile 0 -> A

    #pragma unroll 1
    for (int k = 0; k < 32; k += 2) {
        // iteration k: prefetch k+1 into B, process A
        if (k + 1 < 32) LOAD_TILE(dB, tile0 + k + 1)
        TILE_STEP(dA, (k & 1))
        // iteration k+1: prefetch k+2 into A, process B
        if (k + 2 < 32) LOAD_TILE(dA, tile0 + k + 2)
        TILE_STEP(dB, ((k + 1) & 1))
    }

    // ---- reduce sv/sve over the 8 q-lanes of each channel group ----
    #pragma unroll
    for (int off = 4; off > 0; off >>= 1) {
        #pragma unroll
        for (int i = 0; i < 8; ++i) {
            sv[i]  += __shfl_down_sync(0xffffffffu, sv[i],  off, 8);
            sve[i] += __shfl_down_sync(0xffffffffu, sve[i], off, 8);
        }
    }
    if (q == 0) {
        #pragma unroll
        for (int i = 0; i < 8; ++i) {
            atomicAdd(&g_sumc[b * C_ + cg * 8 + i], sv[i]);
            atomicAdd(&g_num [b * C_ + cg * 8 + i], sve[i]);
        }
    }
    if (w == 0) {
        #pragma unroll
        for (int off = 16; off > 0; off >>= 1) {
            run_e += __shfl_down_sync(0xffffffffu, run_e, off);
            run_m += __shfl_down_sync(0xffffffffu, run_m, off);
        }
        if (lane == 0) { atomicAdd(&g_D[b], run_e); atomicAdd(&g_summ[b], run_m); }
    }
    __threadfence();
    __syncthreads();
    if (t == 0) {
        unsigned old = atomicAdd(&g_cnt[b], 1u);
        s_last = (old == NBLK - 1);
    }
    __syncthreads();
    if (!s_last) return;

    // ================= finalize (last CTA of this batch) =================
    float* ctx   = sm;            // 256  (aliases AL/AM — loop fully done)
    float* bcv   = sm + 256;      // 256
    float* tvs   = sm + 512;      // 128
    float* tg    = sm + 640;      // 128
    float* sout  = sm + 768;      // 256
    float* red_s = sm + 1024;     // 4
    float* red_q = sm + 1028;     // 4
    float* red_a = sm + 1032;     // 8
    float* hid   = sm + 1040;     // 16
    float* o8    = sm + 1056;     // 8
    float* kar   = sm + 1064;     // 4
    float* fvv   = sm + 1072;     // 8
    float* shm   = sm + 1080;     // 1

    const int wp = w;

    const float Dv    = __ldcg(&g_D[b]);
    const float summv = __ldcg(&g_summ[b]);
    const float numv  = __ldcg(&g_num [b * C_ + t]);
    const float sumcv = __ldcg(&g_sumc[b * C_ + t]);

    ctx[t] = numv  * (1.f / Dv);
    bcv[t] = sumcv * (1.f / (float)HW_);
    {
        float s = sumcv * (1.f / (float)HW_);
        #pragma unroll
        for (int off = 16; off > 0; off >>= 1) s += __shfl_down_sync(0xffffffffu, s, off);
        if (lane == 0) red_a[wp] = s;
    }
    __syncthreads();   // all threads have loaded g_* before any re-zero (race fix)

    // re-zero scratch for next graph replay
    g_num [b * C_ + t] = 0.f;
    g_sumc[b * C_ + t] = 0.f;
    if (t == 0) { g_D[b] = 0.f; g_summ[b] = 0.f; g_cnt[b] = 0u; shm[0] = summv * (1.f / (float)HW_); }
    __syncthreads();

    const float aval = (red_a[0] + red_a[1] + red_a[2] + red_a[3] +
                        red_a[4] + red_a[5] + red_a[6] + red_a[7]) * (1.f / (float)C_);
    const float mv = shm[0];

    // conv1 (128x256): warp wp -> planes wp*16..+15
    {
        const float4* ctx4 = reinterpret_cast<const float4*>(ctx);
        const float4 c0 = ctx4[lane];
        const float4 c1 = ctx4[lane + 32];
        #pragma unroll 4
        for (int i = 0; i < 16; ++i) {
            int p = wp * 16 + i;
            const float4* w4 = reinterpret_cast<const float4*>(w_cm1 + p * C_);
            float4 a0 = w4[lane];
            float4 a1 = w4[lane + 32];
            float pr = a0.x * c0.x + a0.y * c0.y + a0.z * c0.z + a0.w * c0.w
                     + a1.x * c1.x + a1.y * c1.y + a1.z * c1.z + a1.w * c1.w;
            #pragma unroll
            for (int off = 16; off > 0; off >>= 1)
                pr += __shfl_down_sync(0xffffffffu, pr, off);
            if (lane == 0) tvs[p] = pr + b_cm1[p];
        }
    }
    __syncthreads();

    // LayerNorm(128) + exact GELU
    {
        float tvv = (t < PLANES) ? tvs[t] : 0.f;
        float s1 = tvv, s2 = tvv * tvv;
        #pragma unroll
        for (int off = 16; off > 0; off >>= 1) {
            s1 += __shfl_down_sync(0xffffffffu, s1, off);
            s2 += __shfl_down_sync(0xffffffffu, s2, off);
        }
        if (t < PLANES && lane == 0) { red_s[wp] = s1; red_q[wp] = s2; }
        __syncthreads();
        if (t < PLANES) {
            float S  = red_s[0] + red_s[1] + red_s[2] + red_s[3];
            float SQ = red_q[0] + red_q[1] + red_q[2] + red_q[3];
            float mu  = S * (1.f / PLANES);
            float var = SQ * (1.f / PLANES) - mu * mu;
            float tn = (tvv - mu) * rsqrtf(var + EPS_) * ln_w[t] + ln_b[t];
            tg[t] = 0.5f * tn * (1.f + erff(tn * 0.70710678118654752f));
        }
    }
    __syncthreads();

    // conv2 (256x128): warp wp -> channels wp*32..+31
    {
        const float4* tg4 = reinterpret_cast<const float4*>(tg);
        const float4 g0 = tg4[lane];
        #pragma unroll 4
        for (int i = 0; i < 32; ++i) {
            int ch = wp * 32 + i;
            const float4* w4 = reinterpret_cast<const float4*>(w_cm2 + ch * PLANES);
            float4 a0 = w4[lane];
            float pr = a0.x * g0.x + a0.y * g0.y + a0.z * g0.z + a0.w * g0.w;
            #pragma unroll
            for (int off = 16; off > 0; off >>= 1)
                pr += __shfl_down_sync(0xffffffffu, pr, off);
            if (lane == 0)
                sout[ch] = bcv[ch] + pr + b_cm2[ch] + ((ch & 1) ? mv : aval);
        }
    }
    __syncthreads();

    // net1 (16x256): warp wp -> hidden wp*2, wp*2+1
    {
        const float4* so4 = reinterpret_cast<const float4*>(sout);
        const float4 s0 = so4[lane];
        const float4 s1v = so4[lane + 32];
        #pragma unroll
        for (int jj = 0; jj < 2; ++jj) {
            int hh = wp * 2 + jj;
            const float4* w4 = reinterpret_cast<const float4*>(w_net1 + hh * C_);
            float4 a0 = w4[lane];
            float4 a1 = w4[lane + 32];
            float pr = a0.x * s0.x + a0.y * s0.y + a0.z * s0.z + a0.w * s0.w
                     + a1.x * s1v.x + a1.y * s1v.y + a1.z * s1v.z + a1.w * s1v.w;
            #pragma unroll
            for (int off = 16; off > 0; off >>= 1)
                pr += __shfl_down_sync(0xffffffffu, pr, off);
            if (lane == 0) hid[hh] = fmaxf(pr, 0.f);
        }
    }
    __syncthreads();

    if (t < K_) {
        float o = 0.f;
        #pragma unroll
        for (int q2 = 0; q2 < HIDDEN; ++q2) o = fmaf(hid[q2], w_net2[t * HIDDEN + q2], o);
        o8[t] = o;
    }
    __syncthreads();
    if (t < ATT_CH) {
        float ka = 0.f;
        #pragma unroll
        for (int k = 0; k < K_; ++k) ka = fmaf(o8[k], w_fc[t * K_ + k], ka);
        ka = (ka - bn_mean[t]) * rsqrtf(bn_var[t] + EPS_) * bn_w[t] + bn_b[t];
        kar[t] = fmaxf(ka, 0.f);
    }
    __syncthreads();
    if (t < K_) {
        float kk = 0.f;
        #pragma unroll
        for (int q2 = 0; q2 < ATT_CH; ++q2) kk = fmaf(kar[q2], w_kfc[t * ATT_CH + q2], kk);
        float ker = 1.f / (1.f + __expf(-kk));
        fvv[t] = o8[t] * ker * (1.f / 30.f);
    }
    __syncthreads();
    if (t == 0) {
        float mx = -1e30f;
        #pragma unroll
        for (int k = 0; k < K_; ++k) mx = fmaxf(mx, fvv[k]);
        float e[K_], s = 0.f;
        #pragma unroll
        for (int k = 0; k < K_; ++k) { e[k] = __expf(fvv[k] - mx); s += e[k]; }
        float inv = 1.f / s;
        #pragma unroll
        for (int k = 0; k < K_; ++k) out[b * K_ + k] = e[k] * inv;
    }
}

// ---------------- launch ----------------
extern "C" void kernel_launch(void* const* d_in, const int* in_sizes, int n_in,
                              void* d_out, int out_size) {
    const float* x      = (const float*)d_in[0];
    const float* w_mask = (const float*)d_in[1];
    const float* b_mask = (const float*)d_in[2];
    const float* w_cm1  = (const float*)d_in[3];
    const float* b_cm1  = (const float*)d_in[4];
    const float* ln_w   = (const float*)d_in[5];
    const float* ln_b   = (const float*)d_in[6];
    const float* w_cm2  = (const float*)d_in[7];
    const float* b_cm2  = (const float*)d_in[8];
    const float* w_net1 = (const float*)d_in[9];
    const float* w_net2 = (const float*)d_in[10];
    const float* w_fc   = (const float*)d_in[11];
    const float* bn_w   = (const float*)d_in[12];
    const float* bn_b   = (const float*)d_in[13];
    const float* bn_mean= (const float*)d_in[14];
    const float* bn_var = (const float*)d_in[15];
    const float* w_kfc  = (const float*)d_in[16];
    float* out = (float*)d_out;

    fused<<<B_ * NBLK, 256>>>(x, w_mask, b_mask,
                          w_cm1, b_cm1, ln_w, ln_b, w_cm2, b_cm2,
                          w_net1, w_net2, w_fc, bn_w, bn_b, bn_mean, bn_var,
                          w_kfc, out);
}